// round 2
// baseline (speedup 1.0000x reference)
#include <cuda_runtime.h>
#include <cuda_bf16.h>
#include <float.h>
#include <math.h>

#define NN 50000
#define DD 128
#define HH 8
#define HDIM 16
#define EE 800000
#define EDIM 4
#define GROUPS 8
#define EPS_GN 1e-5f

// ---------------- scratch (static device globals; no allocation) ----------------
__device__ __align__(16) float g_q[NN * DD];
__device__ __align__(16) float g_k[NN * DD];
__device__ __align__(16) float g_v[NN * DD];
__device__ __align__(16) float g_attn[EE * HH];
__device__ __align__(16) float g_max[NN * HH];
__device__ __align__(16) float g_sum[NN * HH];
__device__ __align__(16) float g_agg[NN * DD];

// ---------------- helpers ----------------
__device__ __forceinline__ float atomicMaxFloat(float* addr, float value) {
    if (value >= 0.0f)
        return __int_as_float(atomicMax((int*)addr, __float_as_int(value)));
    else
        return __uint_as_float(atomicMin((unsigned int*)addr, __float_as_uint(value)));
}

// ---------------- kernel 0: init scratch ----------------
__global__ void init_kernel() {
    int i = blockIdx.x * blockDim.x + threadIdx.x;
    if (i < NN * DD) g_agg[i] = 0.0f;
    if (i < NN * HH) {
        g_max[i] = -FLT_MAX;
        g_sum[i] = 0.0f;
    }
}

// ---------------- kernel 1: fused Q/K/V GEMM ----------------
// block = 256 threads, computes 32 rows x 128 cols.
__global__ void qkv_kernel(const float* __restrict__ x,
                           const float* __restrict__ Wq, const float* __restrict__ bq,
                           const float* __restrict__ Wk, const float* __restrict__ bk,
                           const float* __restrict__ Wv, const float* __restrict__ bv) {
    __shared__ float xs[32 * 128];   // 16 KB
    __shared__ float ws[64 * 128];   // 32 KB

    const float* W;
    const float* b;
    float* out;
    int which = blockIdx.y;
    if (which == 0)      { W = Wq; b = bq; out = g_q; }
    else if (which == 1) { W = Wk; b = bk; out = g_k; }
    else                 { W = Wv; b = bv; out = g_v; }

    const int row0 = blockIdx.x * 32;
    const int tid  = threadIdx.x;

    for (int i = tid; i < 32 * 32; i += 256) {
        int r  = i >> 5;
        int c4 = i & 31;
        float4 val = make_float4(0.f, 0.f, 0.f, 0.f);
        if (row0 + r < NN) val = ((const float4*)x)[(size_t)(row0 + r) * 32 + c4];
        ((float4*)xs)[i] = val;
    }

    const int trow = tid >> 5;
    const int tcol = tid & 31;
    const int r = trow * 4;
    const int c = tcol * 4;

    float acc[4][4];
#pragma unroll
    for (int i = 0; i < 4; i++) {
#pragma unroll
        for (int j = 0; j < 4; j++) acc[i][j] = b[c + j];
    }

    for (int kk = 0; kk < 128; kk += 64) {
        __syncthreads();
        for (int i = tid; i < 64 * 32; i += 256)
            ((float4*)ws)[i] = ((const float4*)W)[kk * 32 + i];
        __syncthreads();

#pragma unroll 8
        for (int k = 0; k < 64; k++) {
            float4 wv4 = ((float4*)ws)[k * 32 + tcol];
#pragma unroll
            for (int i = 0; i < 4; i++) {
                float a = xs[(r + i) * 128 + kk + k];
                acc[i][0] = fmaf(a, wv4.x, acc[i][0]);
                acc[i][1] = fmaf(a, wv4.y, acc[i][1]);
                acc[i][2] = fmaf(a, wv4.z, acc[i][2]);
                acc[i][3] = fmaf(a, wv4.w, acc[i][3]);
            }
        }
    }

#pragma unroll
    for (int i = 0; i < 4; i++) {
        if (row0 + r + i < NN) {
            float4 o = make_float4(acc[i][0], acc[i][1], acc[i][2], acc[i][3]);
            ((float4*)out)[(size_t)(row0 + r + i) * 32 + tcol] = o;
        }
    }
}

// ---------------- kernel 2: edge logits + atomic max ----------------
// one warp per edge; lane handles 4 dims; head = lane/4; shfl reduce within head group.
__global__ void edge_logits_kernel(const int* __restrict__ ei,
                                   const float* __restrict__ edge_attr,
                                   const float* __restrict__ We,
                                   const float* __restrict__ be) {
    __shared__ float we_s[EDIM * HH];
    __shared__ float be_s[HH];
    if (threadIdx.x < EDIM * HH) we_s[threadIdx.x] = We[threadIdx.x];
    if (threadIdx.x < HH)        be_s[threadIdx.x] = be[threadIdx.x];
    __syncthreads();

    int warp = (blockIdx.x * blockDim.x + threadIdx.x) >> 5;
    if (warp >= EE) return;
    int lane = threadIdx.x & 31;

    int src = ei[warp];
    int dst = ei[EE + warp];

    float4 qd = ((const float4*)g_q)[(size_t)dst * 32 + lane];
    float4 kd = ((const float4*)g_k)[(size_t)src * 32 + lane];
    float p = qd.x * kd.x + qd.y * kd.y + qd.z * kd.z + qd.w * kd.w;
    p += __shfl_xor_sync(0xffffffffu, p, 1);
    p += __shfl_xor_sync(0xffffffffu, p, 2);

    float4 ea = make_float4(0.f, 0.f, 0.f, 0.f);
    if (lane == 0) ea = ((const float4*)edge_attr)[warp];
    ea.x = __shfl_sync(0xffffffffu, ea.x, 0);
    ea.y = __shfl_sync(0xffffffffu, ea.y, 0);
    ea.z = __shfl_sync(0xffffffffu, ea.z, 0);
    ea.w = __shfl_sync(0xffffffffu, ea.w, 0);

    if ((lane & 3) == 0) {
        int h = lane >> 2;
        float val = p * 0.25f
                  + ea.x * we_s[0 * HH + h] + ea.y * we_s[1 * HH + h]
                  + ea.z * we_s[2 * HH + h] + ea.w * we_s[3 * HH + h]
                  + be_s[h];
        g_attn[(size_t)warp * HH + h] = val;
        atomicMaxFloat(&g_max[(size_t)dst * HH + h], val);
    }
}

// ---------------- kernel 3: exp + atomic sum ----------------
__global__ void exp_sum_kernel(const int* __restrict__ ei) {
    int idx = blockIdx.x * blockDim.x + threadIdx.x;
    if (idx >= EE * HH) return;
    int e = idx >> 3;
    int h = idx & 7;
    int dst = ei[EE + e];
    float ex = expf(g_attn[idx] - g_max[(size_t)dst * HH + h]);
    g_attn[idx] = ex;
    atomicAdd(&g_sum[(size_t)dst * HH + h], ex);
}

// ---------------- kernel 4: weighted aggregation ----------------
// one warp per edge; lane handles 4 dims, head = lane/4
__global__ void agg_kernel(const int* __restrict__ ei) {
    int warp = (blockIdx.x * blockDim.x + threadIdx.x) >> 5;
    if (warp >= EE) return;
    int lane = threadIdx.x & 31;

    int src = ei[warp];
    int dst = ei[EE + warp];
    int h = lane >> 2;

    float ex = g_attn[(size_t)warp * HH + h];
    float s  = g_sum[(size_t)dst * HH + h];
    float a  = ex / fmaxf(s, 1e-6f);

    float4 vv = ((const float4*)g_v)[(size_t)src * 32 + lane];
    float* o = &g_agg[(size_t)dst * 128 + lane * 4];
    atomicAdd(o + 0, a * vv.x);
    atomicAdd(o + 1, a * vv.y);
    atomicAdd(o + 2, a * vv.z);
    atomicAdd(o + 3, a * vv.w);
}

// ---------------- kernel 5: Wo GEMM + GroupNorm epilogue ----------------
__global__ void out_gn_kernel(const float* __restrict__ Wo, const float* __restrict__ bo,
                              const float* __restrict__ gamma, const float* __restrict__ beta,
                              float* __restrict__ out) {
    __shared__ float xs[32 * 128];
    __shared__ float ws[64 * 128];

    const int row0 = blockIdx.x * 32;
    const int tid  = threadIdx.x;

    for (int i = tid; i < 32 * 32; i += 256) {
        int r  = i >> 5;
        int c4 = i & 31;
        float4 val = make_float4(0.f, 0.f, 0.f, 0.f);
        if (row0 + r < NN) val = ((const float4*)g_agg)[(size_t)(row0 + r) * 32 + c4];
        ((float4*)xs)[i] = val;
    }

    const int trow = tid >> 5;
    const int tcol = tid & 31;
    const int r = trow * 4;
    const int c = tcol * 4;

    float acc[4][4];
#pragma unroll
    for (int i = 0; i < 4; i++) {
#pragma unroll
        for (int j = 0; j < 4; j++) acc[i][j] = bo[c + j];
    }

    for (int kk = 0; kk < 128; kk += 64) {
        __syncthreads();
        for (int i = tid; i < 64 * 32; i += 256)
            ((float4*)ws)[i] = ((const float4*)Wo)[kk * 32 + i];
        __syncthreads();

#pragma unroll 8
        for (int k = 0; k < 64; k++) {
            float4 wv4 = ((float4*)ws)[k * 32 + tcol];
#pragma unroll
            for (int i = 0; i < 4; i++) {
                float a = xs[(r + i) * 128 + kk + k];
                acc[i][0] = fmaf(a, wv4.x, acc[i][0]);
                acc[i][1] = fmaf(a, wv4.y, acc[i][1]);
                acc[i][2] = fmaf(a, wv4.z, acc[i][2]);
                acc[i][3] = fmaf(a, wv4.w, acc[i][3]);
            }
        }
    }

    __syncthreads();
#pragma unroll
    for (int i = 0; i < 4; i++) {
#pragma unroll
        for (int j = 0; j < 4; j++) xs[(r + i) * 128 + c + j] = acc[i][j];
    }
    __syncthreads();

    int srow = tid >> 3;
    int grp  = tid & 7;
    float s = 0.f, s2 = 0.f;
#pragma unroll
    for (int j = 0; j < 16; j++) {
        float v = xs[srow * 128 + grp * 16 + j];
        s += v;
        s2 += v * v;
    }
    float mu  = s * (1.0f / 16.0f);
    float var = s2 * (1.0f / 16.0f) - mu * mu;
    float inv = rsqrtf(var + EPS_GN);

    if (row0 + srow < NN) {
        float* orow = out + (size_t)(row0 + srow) * 128;
#pragma unroll
        for (int j4 = 0; j4 < 4; j4++) {
            int ch0 = grp * 16 + j4 * 4;
            float4 g4 = ((const float4*)gamma)[ch0 >> 2];
            float4 b4 = ((const float4*)beta)[ch0 >> 2];
            float4 o;
            o.x = (xs[srow * 128 + ch0 + 0] - mu) * inv * g4.x + b4.x;
            o.y = (xs[srow * 128 + ch0 + 1] - mu) * inv * g4.y + b4.y;
            o.z = (xs[srow * 128 + ch0 + 2] - mu) * inv * g4.z + b4.z;
            o.w = (xs[srow * 128 + ch0 + 3] - mu) * inv * g4.w + b4.w;
            ((float4*)orow)[ch0 >> 2] = o;
        }
    }
}

// ---------------- launch ----------------
extern "C" void kernel_launch(void* const* d_in, const int* in_sizes, int n_in,
                              void* d_out, int out_size) {
    const float* x         = (const float*)d_in[0];
    const int*   ei        = (const int*)d_in[1];   // int32: JAX downcasts int64 without x64 mode
    const float* edge_attr = (const float*)d_in[2];
    const float* Wq        = (const float*)d_in[3];
    const float* bq        = (const float*)d_in[4];
    const float* Wk        = (const float*)d_in[5];
    const float* bk        = (const float*)d_in[6];
    const float* Wv        = (const float*)d_in[7];
    const float* bv        = (const float*)d_in[8];
    const float* We        = (const float*)d_in[9];
    const float* be        = (const float*)d_in[10];
    const float* Wo        = (const float*)d_in[11];
    const float* bo        = (const float*)d_in[12];
    const float* gamma     = (const float*)d_in[13];
    const float* beta      = (const float*)d_in[14];
    float* out = (float*)d_out;

    init_kernel<<<(NN * DD + 255) / 256, 256>>>();

    dim3 qkv_grid((NN + 31) / 32, 3);
    qkv_kernel<<<qkv_grid, 256>>>(x, Wq, bq, Wk, bk, Wv, bv);

    edge_logits_kernel<<<(EE * 32) / 256, 256>>>(ei, edge_attr, We, be);

    exp_sum_kernel<<<(EE * HH) / 256, 256>>>(ei);

    agg_kernel<<<(EE * 32) / 256, 256>>>(ei);

    out_gn_kernel<<<(NN + 31) / 32, 256>>>(Wo, bo, gamma, beta, out);
}

// round 3
// speedup vs baseline: 1.2179x; 1.2179x over previous
#include <cuda_runtime.h>
#include <cuda_bf16.h>
#include <float.h>
#include <math.h>

#define NN 50000
#define DD 128
#define HH 8
#define HDIM 16
#define EE 800000
#define EDIM 4
#define GROUPS 8
#define EPS_GN 1e-5f

// ---------------- scratch (static device globals; no allocation) ----------------
__device__ __align__(16) float g_q[NN * DD];
__device__ __align__(16) float g_k[NN * DD];
__device__ __align__(16) float g_v[NN * DD];
__device__ __align__(16) float g_attn[EE * HH];   // unnormalized exp(logit)
__device__ __align__(16) float g_sum[NN * HH];
__device__ __align__(16) float g_agg[NN * DD];

// ---------------- kernel 0: init scratch ----------------
__global__ void init_kernel() {
    int i = blockIdx.x * blockDim.x + threadIdx.x;
    if (i < NN * DD) g_agg[i] = 0.0f;
    if (i < NN * HH) g_sum[i] = 0.0f;
}

// ---------------- kernel 1: fused Q/K/V GEMM (one x-tile load, 3 GEMMs) ------
// block = 256 threads, tile 32 rows x 128 cols, 4x4 register blocking.
__global__ void qkv_kernel(const float* __restrict__ x,
                           const float* __restrict__ Wq, const float* __restrict__ bq,
                           const float* __restrict__ Wk, const float* __restrict__ bk,
                           const float* __restrict__ Wv, const float* __restrict__ bv) {
    __shared__ float xs[32 * 128];   // 16 KB
    __shared__ float ws[64 * 128];   // 32 KB

    const int row0 = blockIdx.x * 32;
    const int tid  = threadIdx.x;

    // load x tile once (32 rows x 128 cols), zero-pad beyond N
    for (int i = tid; i < 32 * 32; i += 256) {
        int r  = i >> 5;
        int c4 = i & 31;
        float4 val = make_float4(0.f, 0.f, 0.f, 0.f);
        if (row0 + r < NN) val = ((const float4*)x)[(size_t)(row0 + r) * 32 + c4];
        ((float4*)xs)[i] = val;
    }

    const int trow = tid >> 5;
    const int tcol = tid & 31;
    const int r = trow * 4;
    const int c = tcol * 4;

    const float* Ws[3] = {Wq, Wk, Wv};
    const float* bs[3] = {bq, bk, bv};
    float* outs[3];
    outs[0] = g_q; outs[1] = g_k; outs[2] = g_v;

#pragma unroll 1
    for (int which = 0; which < 3; which++) {
        const float* W = Ws[which];
        const float* b = bs[which];
        float* out = outs[which];

        float acc[4][4];
#pragma unroll
        for (int i = 0; i < 4; i++) {
#pragma unroll
            for (int j = 0; j < 4; j++) acc[i][j] = b[c + j];
        }

#pragma unroll 1
        for (int kk = 0; kk < 128; kk += 64) {
            __syncthreads();
            for (int i = tid; i < 64 * 32; i += 256)
                ((float4*)ws)[i] = ((const float4*)W)[kk * 32 + i];
            __syncthreads();

#pragma unroll 8
            for (int k = 0; k < 64; k++) {
                float4 wv4 = ((float4*)ws)[k * 32 + tcol];
#pragma unroll
                for (int i = 0; i < 4; i++) {
                    float a = xs[(r + i) * 128 + kk + k];
                    acc[i][0] = fmaf(a, wv4.x, acc[i][0]);
                    acc[i][1] = fmaf(a, wv4.y, acc[i][1]);
                    acc[i][2] = fmaf(a, wv4.z, acc[i][2]);
                    acc[i][3] = fmaf(a, wv4.w, acc[i][3]);
                }
            }
        }

#pragma unroll
        for (int i = 0; i < 4; i++) {
            if (row0 + r + i < NN) {
                float4 o = make_float4(acc[i][0], acc[i][1], acc[i][2], acc[i][3]);
                ((float4*)out)[(size_t)(row0 + r + i) * 32 + tcol] = o;
            }
        }
    }
}

// ---------------- kernel 2: edge logits -> exp -> scatter sum (no max pass) ---
// one warp per edge; lane handles 4 dims; head = lane/4; shfl reduce within head group.
__global__ void edge_logits_kernel(const int* __restrict__ ei,
                                   const float* __restrict__ edge_attr,
                                   const float* __restrict__ We,
                                   const float* __restrict__ be) {
    __shared__ float we_s[EDIM * HH];
    __shared__ float be_s[HH];
    if (threadIdx.x < EDIM * HH) we_s[threadIdx.x] = We[threadIdx.x];
    if (threadIdx.x < HH)        be_s[threadIdx.x] = be[threadIdx.x];
    __syncthreads();

    int warp = (blockIdx.x * blockDim.x + threadIdx.x) >> 5;
    if (warp >= EE) return;
    int lane = threadIdx.x & 31;

    int src = ei[warp];
    int dst = ei[EE + warp];

    float4 qd = ((const float4*)g_q)[(size_t)dst * 32 + lane];
    float4 kd = ((const float4*)g_k)[(size_t)src * 32 + lane];
    float p = qd.x * kd.x + qd.y * kd.y + qd.z * kd.z + qd.w * kd.w;
    p += __shfl_xor_sync(0xffffffffu, p, 1);
    p += __shfl_xor_sync(0xffffffffu, p, 2);

    float4 ea = make_float4(0.f, 0.f, 0.f, 0.f);
    if (lane == 0) ea = ((const float4*)edge_attr)[warp];
    ea.x = __shfl_sync(0xffffffffu, ea.x, 0);
    ea.y = __shfl_sync(0xffffffffu, ea.y, 0);
    ea.z = __shfl_sync(0xffffffffu, ea.z, 0);
    ea.w = __shfl_sync(0xffffffffu, ea.w, 0);

    if ((lane & 3) == 0) {
        int h = lane >> 2;
        float val = p * 0.25f
                  + ea.x * we_s[0 * HH + h] + ea.y * we_s[1 * HH + h]
                  + ea.z * we_s[2 * HH + h] + ea.w * we_s[3 * HH + h]
                  + be_s[h];
        // softmax shift-invariance: skip the max pass, exponentiate directly.
        float ex = __expf(val);
        g_attn[(size_t)warp * HH + h] = ex;
        atomicAdd(&g_sum[(size_t)dst * HH + h], ex);
    }
}

// ---------------- kernel 3: weighted aggregation (vectorized RED) ------------
// one warp per edge; lane handles 4 dims, head = lane/4
__global__ void agg_kernel(const int* __restrict__ ei) {
    int warp = (blockIdx.x * blockDim.x + threadIdx.x) >> 5;
    if (warp >= EE) return;
    int lane = threadIdx.x & 31;

    int src = ei[warp];
    int dst = ei[EE + warp];
    int h = lane >> 2;

    float ex = g_attn[(size_t)warp * HH + h];
    float s  = g_sum[(size_t)dst * HH + h];
    float a  = ex / fmaxf(s, 1e-6f);

    float4 vv = ((const float4*)g_v)[(size_t)src * 32 + lane];
    float* o = &g_agg[(size_t)dst * 128 + lane * 4];
    asm volatile("red.global.add.v4.f32 [%0], {%1, %2, %3, %4};"
                 :: "l"(o), "f"(a * vv.x), "f"(a * vv.y), "f"(a * vv.z), "f"(a * vv.w)
                 : "memory");
}

// ---------------- kernel 4: Wo GEMM + GroupNorm epilogue ----------------
__global__ void out_gn_kernel(const float* __restrict__ Wo, const float* __restrict__ bo,
                              const float* __restrict__ gamma, const float* __restrict__ beta,
                              float* __restrict__ out) {
    __shared__ float xs[32 * 128];
    __shared__ float ws[64 * 128];

    const int row0 = blockIdx.x * 32;
    const int tid  = threadIdx.x;

    for (int i = tid; i < 32 * 32; i += 256) {
        int r  = i >> 5;
        int c4 = i & 31;
        float4 val = make_float4(0.f, 0.f, 0.f, 0.f);
        if (row0 + r < NN) val = ((const float4*)g_agg)[(size_t)(row0 + r) * 32 + c4];
        ((float4*)xs)[i] = val;
    }

    const int trow = tid >> 5;
    const int tcol = tid & 31;
    const int r = trow * 4;
    const int c = tcol * 4;

    float acc[4][4];
#pragma unroll
    for (int i = 0; i < 4; i++) {
#pragma unroll
        for (int j = 0; j < 4; j++) acc[i][j] = bo[c + j];
    }

#pragma unroll 1
    for (int kk = 0; kk < 128; kk += 64) {
        __syncthreads();
        for (int i = tid; i < 64 * 32; i += 256)
            ((float4*)ws)[i] = ((const float4*)Wo)[kk * 32 + i];
        __syncthreads();

#pragma unroll 8
        for (int k = 0; k < 64; k++) {
            float4 wv4 = ((float4*)ws)[k * 32 + tcol];
#pragma unroll
            for (int i = 0; i < 4; i++) {
                float a = xs[(r + i) * 128 + kk + k];
                acc[i][0] = fmaf(a, wv4.x, acc[i][0]);
                acc[i][1] = fmaf(a, wv4.y, acc[i][1]);
                acc[i][2] = fmaf(a, wv4.z, acc[i][2]);
                acc[i][3] = fmaf(a, wv4.w, acc[i][3]);
            }
        }
    }

    __syncthreads();
#pragma unroll
    for (int i = 0; i < 4; i++) {
#pragma unroll
        for (int j = 0; j < 4; j++) xs[(r + i) * 128 + c + j] = acc[i][j];
    }
    __syncthreads();

    int srow = tid >> 3;
    int grp  = tid & 7;
    float s = 0.f, s2 = 0.f;
#pragma unroll
    for (int j = 0; j < 16; j++) {
        float v = xs[srow * 128 + grp * 16 + j];
        s += v;
        s2 += v * v;
    }
    float mu  = s * (1.0f / 16.0f);
    float var = s2 * (1.0f / 16.0f) - mu * mu;
    float inv = rsqrtf(var + EPS_GN);

    if (row0 + srow < NN) {
        float* orow = out + (size_t)(row0 + srow) * 128;
#pragma unroll
        for (int j4 = 0; j4 < 4; j4++) {
            int ch0 = grp * 16 + j4 * 4;
            float4 g4 = ((const float4*)gamma)[ch0 >> 2];
            float4 b4 = ((const float4*)beta)[ch0 >> 2];
            float4 o;
            o.x = (xs[srow * 128 + ch0 + 0] - mu) * inv * g4.x + b4.x;
            o.y = (xs[srow * 128 + ch0 + 1] - mu) * inv * g4.y + b4.y;
            o.z = (xs[srow * 128 + ch0 + 2] - mu) * inv * g4.z + b4.z;
            o.w = (xs[srow * 128 + ch0 + 3] - mu) * inv * g4.w + b4.w;
            ((float4*)orow)[ch0 >> 2] = o;
        }
    }
}

// ---------------- launch ----------------
extern "C" void kernel_launch(void* const* d_in, const int* in_sizes, int n_in,
                              void* d_out, int out_size) {
    const float* x         = (const float*)d_in[0];
    const int*   ei        = (const int*)d_in[1];   // int32 (JAX downcasts int64 w/o x64 mode)
    const float* edge_attr = (const float*)d_in[2];
    const float* Wq        = (const float*)d_in[3];
    const float* bq        = (const float*)d_in[4];
    const float* Wk        = (const float*)d_in[5];
    const float* bk        = (const float*)d_in[6];
    const float* Wv        = (const float*)d_in[7];
    const float* bv        = (const float*)d_in[8];
    const float* We        = (const float*)d_in[9];
    const float* be        = (const float*)d_in[10];
    const float* Wo        = (const float*)d_in[11];
    const float* bo        = (const float*)d_in[12];
    const float* gamma     = (const float*)d_in[13];
    const float* beta      = (const float*)d_in[14];
    float* out = (float*)d_out;

    init_kernel<<<(NN * DD + 255) / 256, 256>>>();

    qkv_kernel<<<(NN + 31) / 32, 256>>>(x, Wq, bq, Wk, bk, Wv, bv);

    edge_logits_kernel<<<(EE * 32) / 256, 256>>>(ei, edge_attr, We, be);

    agg_kernel<<<(EE * 32) / 256, 256>>>(ei);

    out_gn_kernel<<<(NN + 31) / 32, 256>>>(Wo, bo, gamma, beta, out);
}

// round 4
// speedup vs baseline: 1.3635x; 1.1196x over previous
#include <cuda_runtime.h>
#include <cuda_bf16.h>
#include <float.h>
#include <math.h>
#include <stdint.h>

#define NN 50000
#define DD 128
#define HH 8
#define HDIM 16
#define EE 800000
#define EDIM 4
#define GROUPS 8
#define EPS_GN 1e-5f

// ---------------- scratch (static device globals; no allocation) ----------------
__device__ __align__(16) float g_q[NN * DD];
__device__ __align__(16) float g_k[NN * DD];
__device__ __align__(16) float g_v[NN * DD];
__device__ __align__(16) float g_attn[EE * HH];   // unnormalized exp(logit)
__device__ __align__(16) float g_sum[NN * HH];
__device__ __align__(16) float g_agg[NN * DD];

// ---------------- kernel 0: init scratch ----------------
__global__ void init_kernel() {
    int i = blockIdx.x * blockDim.x + threadIdx.x;
    if (i < NN * DD) g_agg[i] = 0.0f;
    if (i < NN * HH) g_sum[i] = 0.0f;
}

// ---------------- tf32 helpers ----------------
__device__ __forceinline__ uint32_t f32_to_tf32(float f) {
    uint32_t r;
    asm("cvt.rna.tf32.f32 %0, %1;" : "=r"(r) : "f"(f));
    return r;
}

__device__ __forceinline__ void mma_tf32(float* c, const uint32_t* a, const uint32_t* b) {
    asm volatile(
        "mma.sync.aligned.m16n8k8.row.col.f32.tf32.tf32.f32 "
        "{%0,%1,%2,%3}, {%4,%5,%6,%7}, {%8,%9}, {%0,%1,%2,%3};"
        : "+f"(c[0]), "+f"(c[1]), "+f"(c[2]), "+f"(c[3])
        : "r"(a[0]), "r"(a[1]), "r"(a[2]), "r"(a[3]), "r"(b[0]), "r"(b[1]));
}

// ---------------- kernel 1: tf32 tensor-core Q/K/V GEMM ----------------
// Block: 256 thr (8 warps, 4x2), output tile 128 rows x 128 cols, K chunks of 32.
// Smem strides: xs 44 floats/row (176B, 16B-aligned, conflict-free A frags),
//               ws 136 floats/row (544B, conflict-free B frags).
#define XS_STRIDE 44
#define WS_STRIDE 136

__global__ void __launch_bounds__(256) qkv_tc_kernel(
        const float* __restrict__ x,
        const float* __restrict__ Wq, const float* __restrict__ bq,
        const float* __restrict__ Wk, const float* __restrict__ bk,
        const float* __restrict__ Wv, const float* __restrict__ bv) {
    __shared__ float xs[128 * XS_STRIDE];   // 22.5 KB
    __shared__ float ws[32 * WS_STRIDE];    // 17.4 KB

    const int tid  = threadIdx.x;
    const int wid  = tid >> 5;
    const int lane = tid & 31;
    const int g    = lane >> 2;   // 0..7
    const int tg   = lane & 3;    // 0..3
    const int row0 = blockIdx.x * 128;
    const int wm0  = (wid >> 1) * 32;   // warp row offset (0,32,64,96)
    const int wn0  = (wid & 1) * 64;    // warp col offset (0,64)

    const float* Ws[3] = {Wq, Wk, Wv};
    const float* bs[3] = {bq, bk, bv};
    float* outs[3];
    outs[0] = g_q; outs[1] = g_k; outs[2] = g_v;

#pragma unroll 1
    for (int which = 0; which < 3; which++) {
        const float* W = Ws[which];
        const float* bb = bs[which];
        float* out = outs[which];

        // acc[mt][nt][4]: mt in {0,1} (16-row tiles), nt in 0..7 (8-col tiles)
        float acc[2][8][4];
#pragma unroll
        for (int nt = 0; nt < 8; nt++) {
            int n = wn0 + nt * 8 + tg * 2;
            float b0 = bb[n], b1 = bb[n + 1];
#pragma unroll
            for (int mt = 0; mt < 2; mt++) {
                acc[mt][nt][0] = b0; acc[mt][nt][1] = b1;
                acc[mt][nt][2] = b0; acc[mt][nt][3] = b1;
            }
        }

#pragma unroll 1
        for (int kk = 0; kk < 128; kk += 32) {
            __syncthreads();
            // x chunk: 128 rows x 32 cols -> xs (tf32-rounded)
            for (int i = tid; i < 128 * 8; i += 256) {
                int r = i >> 3, c4 = i & 7;
                float4 v = make_float4(0.f, 0.f, 0.f, 0.f);
                if (row0 + r < NN)
                    v = ((const float4*)x)[(size_t)(row0 + r) * 32 + (kk >> 2) + c4];
                uint32_t* d = (uint32_t*)(xs + r * XS_STRIDE + c4 * 4);
                d[0] = f32_to_tf32(v.x); d[1] = f32_to_tf32(v.y);
                d[2] = f32_to_tf32(v.z); d[3] = f32_to_tf32(v.w);
            }
            // W chunk: 32 k-rows x 128 cols -> ws (tf32-rounded)
            for (int i = tid; i < 32 * 32; i += 256) {
                int r = i >> 5, c4 = i & 31;
                float4 v = ((const float4*)W)[(size_t)(kk + r) * 32 + c4];
                uint32_t* d = (uint32_t*)(ws + r * WS_STRIDE + c4 * 4);
                d[0] = f32_to_tf32(v.x); d[1] = f32_to_tf32(v.y);
                d[2] = f32_to_tf32(v.z); d[3] = f32_to_tf32(v.w);
            }
            __syncthreads();

#pragma unroll
            for (int kk2 = 0; kk2 < 32; kk2 += 8) {
                uint32_t afr[2][4];
#pragma unroll
                for (int mt = 0; mt < 2; mt++) {
                    const uint32_t* xr  = (const uint32_t*)(xs + (wm0 + mt * 16 + g) * XS_STRIDE + kk2);
                    const uint32_t* xr8 = (const uint32_t*)(xs + (wm0 + mt * 16 + g + 8) * XS_STRIDE + kk2);
                    afr[mt][0] = xr[tg];
                    afr[mt][1] = xr8[tg];
                    afr[mt][2] = xr[tg + 4];
                    afr[mt][3] = xr8[tg + 4];
                }
#pragma unroll
                for (int nt = 0; nt < 8; nt++) {
                    uint32_t bfr[2];
                    bfr[0] = ((const uint32_t*)(ws + (kk2 + tg) * WS_STRIDE))[wn0 + nt * 8 + g];
                    bfr[1] = ((const uint32_t*)(ws + (kk2 + tg + 4) * WS_STRIDE))[wn0 + nt * 8 + g];
                    mma_tf32(acc[0][nt], afr[0], bfr);
                    mma_tf32(acc[1][nt], afr[1], bfr);
                }
            }
        }

        // store: rows row0+wm0+mt*16+g (+8), cols wn0+nt*8+tg*2 (+1)
        __syncthreads();
#pragma unroll
        for (int mt = 0; mt < 2; mt++) {
            int rA = row0 + wm0 + mt * 16 + g;
            int rB = rA + 8;
#pragma unroll
            for (int nt = 0; nt < 8; nt++) {
                int n = wn0 + nt * 8 + tg * 2;
                if (rA < NN)
                    *(float2*)(out + (size_t)rA * 128 + n) = make_float2(acc[mt][nt][0], acc[mt][nt][1]);
                if (rB < NN)
                    *(float2*)(out + (size_t)rB * 128 + n) = make_float2(acc[mt][nt][2], acc[mt][nt][3]);
            }
        }
    }
}

// ---------------- kernel 2: edge logits -> exp -> scatter sum (no max pass) ---
__global__ void edge_logits_kernel(const int* __restrict__ ei,
                                   const float* __restrict__ edge_attr,
                                   const float* __restrict__ We,
                                   const float* __restrict__ be) {
    __shared__ float we_s[EDIM * HH];
    __shared__ float be_s[HH];
    if (threadIdx.x < EDIM * HH) we_s[threadIdx.x] = We[threadIdx.x];
    if (threadIdx.x < HH)        be_s[threadIdx.x] = be[threadIdx.x];
    __syncthreads();

    int warp = (blockIdx.x * blockDim.x + threadIdx.x) >> 5;
    if (warp >= EE) return;
    int lane = threadIdx.x & 31;

    int src = ei[warp];
    int dst = ei[EE + warp];

    float4 qd = ((const float4*)g_q)[(size_t)dst * 32 + lane];
    float4 kd = ((const float4*)g_k)[(size_t)src * 32 + lane];
    float p = qd.x * kd.x + qd.y * kd.y + qd.z * kd.z + qd.w * kd.w;
    p += __shfl_xor_sync(0xffffffffu, p, 1);
    p += __shfl_xor_sync(0xffffffffu, p, 2);

    float4 ea = make_float4(0.f, 0.f, 0.f, 0.f);
    if (lane == 0) ea = ((const float4*)edge_attr)[warp];
    ea.x = __shfl_sync(0xffffffffu, ea.x, 0);
    ea.y = __shfl_sync(0xffffffffu, ea.y, 0);
    ea.z = __shfl_sync(0xffffffffu, ea.z, 0);
    ea.w = __shfl_sync(0xffffffffu, ea.w, 0);

    if ((lane & 3) == 0) {
        int h = lane >> 2;
        float val = p * 0.25f
                  + ea.x * we_s[0 * HH + h] + ea.y * we_s[1 * HH + h]
                  + ea.z * we_s[2 * HH + h] + ea.w * we_s[3 * HH + h]
                  + be_s[h];
        float ex = __expf(val);   // softmax shift-invariance: no max pass needed
        g_attn[(size_t)warp * HH + h] = ex;
        atomicAdd(&g_sum[(size_t)dst * HH + h], ex);
    }
}

// ---------------- kernel 3: weighted aggregation (vectorized RED) ------------
__global__ void agg_kernel(const int* __restrict__ ei) {
    int warp = (blockIdx.x * blockDim.x + threadIdx.x) >> 5;
    if (warp >= EE) return;
    int lane = threadIdx.x & 31;

    int src = ei[warp];
    int dst = ei[EE + warp];
    int h = lane >> 2;

    float ex = g_attn[(size_t)warp * HH + h];
    float s  = g_sum[(size_t)dst * HH + h];
    float a  = ex / fmaxf(s, 1e-6f);

    float4 vv = ((const float4*)g_v)[(size_t)src * 32 + lane];
    float* o = &g_agg[(size_t)dst * 128 + lane * 4];
    asm volatile("red.global.add.v4.f32 [%0], {%1, %2, %3, %4};"
                 :: "l"(o), "f"(a * vv.x), "f"(a * vv.y), "f"(a * vv.z), "f"(a * vv.w)
                 : "memory");
}

// ---------------- kernel 4: Wo GEMM + GroupNorm epilogue (fp32 SIMT) ---------
__global__ void out_gn_kernel(const float* __restrict__ Wo, const float* __restrict__ bo,
                              const float* __restrict__ gamma, const float* __restrict__ beta,
                              float* __restrict__ out) {
    __shared__ float xs[32 * 128];
    __shared__ float ws[64 * 128];

    const int row0 = blockIdx.x * 32;
    const int tid  = threadIdx.x;

    for (int i = tid; i < 32 * 32; i += 256) {
        int r  = i >> 5;
        int c4 = i & 31;
        float4 val = make_float4(0.f, 0.f, 0.f, 0.f);
        if (row0 + r < NN) val = ((const float4*)g_agg)[(size_t)(row0 + r) * 32 + c4];
        ((float4*)xs)[i] = val;
    }

    const int trow = tid >> 5;
    const int tcol = tid & 31;
    const int r = trow * 4;
    const int c = tcol * 4;

    float acc[4][4];
#pragma unroll
    for (int i = 0; i < 4; i++) {
#pragma unroll
        for (int j = 0; j < 4; j++) acc[i][j] = bo[c + j];
    }

#pragma unroll 1
    for (int kk = 0; kk < 128; kk += 64) {
        __syncthreads();
        for (int i = tid; i < 64 * 32; i += 256)
            ((float4*)ws)[i] = ((const float4*)Wo)[kk * 32 + i];
        __syncthreads();

#pragma unroll 8
        for (int k = 0; k < 64; k++) {
            float4 wv4 = ((float4*)ws)[k * 32 + tcol];
#pragma unroll
            for (int i = 0; i < 4; i++) {
                float a = xs[(r + i) * 128 + kk + k];
                acc[i][0] = fmaf(a, wv4.x, acc[i][0]);
                acc[i][1] = fmaf(a, wv4.y, acc[i][1]);
                acc[i][2] = fmaf(a, wv4.z, acc[i][2]);
                acc[i][3] = fmaf(a, wv4.w, acc[i][3]);
            }
        }
    }

    __syncthreads();
#pragma unroll
    for (int i = 0; i < 4; i++) {
#pragma unroll
        for (int j = 0; j < 4; j++) xs[(r + i) * 128 + c + j] = acc[i][j];
    }
    __syncthreads();

    int srow = tid >> 3;
    int grp  = tid & 7;
    float s = 0.f, s2 = 0.f;
#pragma unroll
    for (int j = 0; j < 16; j++) {
        float v = xs[srow * 128 + grp * 16 + j];
        s += v;
        s2 += v * v;
    }
    float mu  = s * (1.0f / 16.0f);
    float var = s2 * (1.0f / 16.0f) - mu * mu;
    float inv = rsqrtf(var + EPS_GN);

    if (row0 + srow < NN) {
        float* orow = out + (size_t)(row0 + srow) * 128;
#pragma unroll
        for (int j4 = 0; j4 < 4; j4++) {
            int ch0 = grp * 16 + j4 * 4;
            float4 g4 = ((const float4*)gamma)[ch0 >> 2];
            float4 b4 = ((const float4*)beta)[ch0 >> 2];
            float4 o;
            o.x = (xs[srow * 128 + ch0 + 0] - mu) * inv * g4.x + b4.x;
            o.y = (xs[srow * 128 + ch0 + 1] - mu) * inv * g4.y + b4.y;
            o.z = (xs[srow * 128 + ch0 + 2] - mu) * inv * g4.z + b4.z;
            o.w = (xs[srow * 128 + ch0 + 3] - mu) * inv * g4.w + b4.w;
            ((float4*)orow)[ch0 >> 2] = o;
        }
    }
}

// ---------------- launch ----------------
extern "C" void kernel_launch(void* const* d_in, const int* in_sizes, int n_in,
                              void* d_out, int out_size) {
    const float* x         = (const float*)d_in[0];
    const int*   ei        = (const int*)d_in[1];   // int32 (JAX downcasts int64 w/o x64 mode)
    const float* edge_attr = (const float*)d_in[2];
    const float* Wq        = (const float*)d_in[3];
    const float* bq        = (const float*)d_in[4];
    const float* Wk        = (const float*)d_in[5];
    const float* bk        = (const float*)d_in[6];
    const float* Wv        = (const float*)d_in[7];
    const float* bv        = (const float*)d_in[8];
    const float* We        = (const float*)d_in[9];
    const float* be        = (const float*)d_in[10];
    const float* Wo        = (const float*)d_in[11];
    const float* bo        = (const float*)d_in[12];
    const float* gamma     = (const float*)d_in[13];
    const float* beta      = (const float*)d_in[14];
    float* out = (float*)d_out;

    init_kernel<<<(NN * DD + 255) / 256, 256>>>();

    qkv_tc_kernel<<<(NN + 127) / 128, 256>>>(x, Wq, bq, Wk, bk, Wv, bv);

    edge_logits_kernel<<<(EE * 32) / 256, 256>>>(ei, edge_attr, We, be);

    agg_kernel<<<(EE * 32) / 256, 256>>>(ei);

    out_gn_kernel<<<(NN + 31) / 32, 256>>>(Wo, bo, gamma, beta, out);
}

// round 5
// speedup vs baseline: 1.6567x; 1.2150x over previous
#include <cuda_runtime.h>
#include <cuda_bf16.h>
#include <float.h>
#include <math.h>
#include <stdint.h>

#define NN 50000
#define DD 128
#define HH 8
#define HDIM 16
#define EE 800000
#define EDIM 4
#define GROUPS 8
#define EPS_GN 1e-5f

// ---------------- scratch (static device globals; no allocation) ----------------
__device__ __align__(16) float g_q[NN * DD];
__device__ __align__(16) float g_k[NN * DD];
__device__ __align__(16) float g_v[NN * DD];
__device__ __align__(16) float g_agg[NN * DD];
__device__ int g_deg[NN];
__device__ int g_cur[NN];
__device__ int g_off[NN + 1];
__device__ int g_csr_src[EE];
__device__ __align__(16) float g_csr_bias[(size_t)EE * HH];

// ---------------- tf32 helpers ----------------
__device__ __forceinline__ uint32_t f32_to_tf32(float f) {
    uint32_t r;
    asm("cvt.rna.tf32.f32 %0, %1;" : "=r"(r) : "f"(f));
    return r;
}

__device__ __forceinline__ void mma_tf32(float* c, const uint32_t* a, const uint32_t* b) {
    asm volatile(
        "mma.sync.aligned.m16n8k8.row.col.f32.tf32.tf32.f32 "
        "{%0,%1,%2,%3}, {%4,%5,%6,%7}, {%8,%9}, {%0,%1,%2,%3};"
        : "+f"(c[0]), "+f"(c[1]), "+f"(c[2]), "+f"(c[3])
        : "r"(a[0]), "r"(a[1]), "r"(a[2]), "r"(a[3]), "r"(b[0]), "r"(b[1]));
}

// ---------------- CSR build ----------------
__global__ void zero_kernel() {
    int i = blockIdx.x * blockDim.x + threadIdx.x;
    if (i < NN) { g_deg[i] = 0; g_cur[i] = 0; }
}

__global__ void hist_kernel(const int* __restrict__ ei) {
    int e = blockIdx.x * blockDim.x + threadIdx.x;
    if (e >= EE) return;
    atomicAdd(&g_deg[ei[EE + e]], 1);
}

// single-block exclusive scan of g_deg -> g_off
__global__ void scan_kernel() {
    __shared__ int sdata[1024];
    __shared__ int s_running;
    const int tid = threadIdx.x;
    if (tid == 0) s_running = 0;
    __syncthreads();

    for (int base = 0; base < NN; base += 1024) {
        int v = (base + tid < NN) ? g_deg[base + tid] : 0;
        sdata[tid] = v;
        __syncthreads();
#pragma unroll
        for (int s = 1; s < 1024; s <<= 1) {
            int t = (tid >= s) ? sdata[tid - s] : 0;
            __syncthreads();
            sdata[tid] += t;
            __syncthreads();
        }
        int incl = sdata[tid];
        int run = s_running;
        if (base + tid < NN) g_off[base + tid] = run + incl - v;
        __syncthreads();
        if (tid == 0) s_running = run + sdata[1023];
        __syncthreads();
    }
    if (tid == 0) g_off[NN] = s_running;
}

// scatter edges into CSR slots; precompute per-edge head bias in CSR order
__global__ void scatter_kernel(const int* __restrict__ ei,
                               const float* __restrict__ edge_attr,
                               const float* __restrict__ We,
                               const float* __restrict__ be) {
    int e = blockIdx.x * blockDim.x + threadIdx.x;
    if (e >= EE) return;
    int src = ei[e];
    int dst = ei[EE + e];
    int slot = g_off[dst] + atomicAdd(&g_cur[dst], 1);
    g_csr_src[slot] = src;

    float4 ea = ((const float4*)edge_attr)[e];
    float* bias = &g_csr_bias[(size_t)slot * HH];
#pragma unroll
    for (int h = 0; h < HH; h += 4) {
        float4 o;
        o.x = ea.x * We[0 * HH + h + 0] + ea.y * We[1 * HH + h + 0]
            + ea.z * We[2 * HH + h + 0] + ea.w * We[3 * HH + h + 0] + be[h + 0];
        o.y = ea.x * We[0 * HH + h + 1] + ea.y * We[1 * HH + h + 1]
            + ea.z * We[2 * HH + h + 1] + ea.w * We[3 * HH + h + 1] + be[h + 1];
        o.z = ea.x * We[0 * HH + h + 2] + ea.y * We[1 * HH + h + 2]
            + ea.z * We[2 * HH + h + 2] + ea.w * We[3 * HH + h + 2] + be[h + 2];
        o.w = ea.x * We[0 * HH + h + 3] + ea.y * We[1 * HH + h + 3]
            + ea.z * We[2 * HH + h + 3] + ea.w * We[3 * HH + h + 3] + be[h + 3];
        *(float4*)(bias + h) = o;
    }
}

// ---------------- tf32 tensor-core Q/K/V GEMM ----------------
#define XS_STRIDE 44
#define WS_STRIDE 136

__global__ void __launch_bounds__(256) qkv_tc_kernel(
        const float* __restrict__ x,
        const float* __restrict__ Wq, const float* __restrict__ bq,
        const float* __restrict__ Wk, const float* __restrict__ bk,
        const float* __restrict__ Wv, const float* __restrict__ bv) {
    __shared__ float xs[128 * XS_STRIDE];
    __shared__ float ws[32 * WS_STRIDE];

    const int tid  = threadIdx.x;
    const int wid  = tid >> 5;
    const int lane = tid & 31;
    const int g    = lane >> 2;
    const int tg   = lane & 3;
    const int row0 = blockIdx.x * 128;
    const int wm0  = (wid >> 1) * 32;
    const int wn0  = (wid & 1) * 64;

    const float* Ws[3] = {Wq, Wk, Wv};
    const float* bs[3] = {bq, bk, bv};
    float* outs[3];
    outs[0] = g_q; outs[1] = g_k; outs[2] = g_v;

#pragma unroll 1
    for (int which = 0; which < 3; which++) {
        const float* W = Ws[which];
        const float* bb = bs[which];
        float* out = outs[which];

        float acc[2][8][4];
#pragma unroll
        for (int nt = 0; nt < 8; nt++) {
            int n = wn0 + nt * 8 + tg * 2;
            float b0 = bb[n], b1 = bb[n + 1];
#pragma unroll
            for (int mt = 0; mt < 2; mt++) {
                acc[mt][nt][0] = b0; acc[mt][nt][1] = b1;
                acc[mt][nt][2] = b0; acc[mt][nt][3] = b1;
            }
        }

#pragma unroll 1
        for (int kk = 0; kk < 128; kk += 32) {
            __syncthreads();
            for (int i = tid; i < 128 * 8; i += 256) {
                int r = i >> 3, c4 = i & 7;
                float4 v = make_float4(0.f, 0.f, 0.f, 0.f);
                if (row0 + r < NN)
                    v = ((const float4*)x)[(size_t)(row0 + r) * 32 + (kk >> 2) + c4];
                uint32_t* d = (uint32_t*)(xs + r * XS_STRIDE + c4 * 4);
                d[0] = f32_to_tf32(v.x); d[1] = f32_to_tf32(v.y);
                d[2] = f32_to_tf32(v.z); d[3] = f32_to_tf32(v.w);
            }
            for (int i = tid; i < 32 * 32; i += 256) {
                int r = i >> 5, c4 = i & 31;
                float4 v = ((const float4*)W)[(size_t)(kk + r) * 32 + c4];
                uint32_t* d = (uint32_t*)(ws + r * WS_STRIDE + c4 * 4);
                d[0] = f32_to_tf32(v.x); d[1] = f32_to_tf32(v.y);
                d[2] = f32_to_tf32(v.z); d[3] = f32_to_tf32(v.w);
            }
            __syncthreads();

#pragma unroll
            for (int kk2 = 0; kk2 < 32; kk2 += 8) {
                uint32_t afr[2][4];
#pragma unroll
                for (int mt = 0; mt < 2; mt++) {
                    const uint32_t* xr  = (const uint32_t*)(xs + (wm0 + mt * 16 + g) * XS_STRIDE + kk2);
                    const uint32_t* xr8 = (const uint32_t*)(xs + (wm0 + mt * 16 + g + 8) * XS_STRIDE + kk2);
                    afr[mt][0] = xr[tg];
                    afr[mt][1] = xr8[tg];
                    afr[mt][2] = xr[tg + 4];
                    afr[mt][3] = xr8[tg + 4];
                }
#pragma unroll
                for (int nt = 0; nt < 8; nt++) {
                    uint32_t bfr[2];
                    bfr[0] = ((const uint32_t*)(ws + (kk2 + tg) * WS_STRIDE))[wn0 + nt * 8 + g];
                    bfr[1] = ((const uint32_t*)(ws + (kk2 + tg + 4) * WS_STRIDE))[wn0 + nt * 8 + g];
                    mma_tf32(acc[0][nt], afr[0], bfr);
                    mma_tf32(acc[1][nt], afr[1], bfr);
                }
            }
        }

        __syncthreads();
#pragma unroll
        for (int mt = 0; mt < 2; mt++) {
            int rA = row0 + wm0 + mt * 16 + g;
            int rB = rA + 8;
#pragma unroll
            for (int nt = 0; nt < 8; nt++) {
                int n = wn0 + nt * 8 + tg * 2;
                if (rA < NN)
                    *(float2*)(out + (size_t)rA * 128 + n) = make_float2(acc[mt][nt][0], acc[mt][nt][1]);
                if (rB < NN)
                    *(float2*)(out + (size_t)rB * 128 + n) = make_float2(acc[mt][nt][2], acc[mt][nt][3]);
            }
        }
    }
}

// ---------------- fused gather: logits -> exp -> weighted sum -> normalize ----
// one warp per dst node; lane = 4 dims, head = lane/4. No atomics.
__global__ void __launch_bounds__(256) gather_kernel() {
    int node = blockIdx.x * 8 + (threadIdx.x >> 5);
    if (node >= NN) return;
    int lane = threadIdx.x & 31;
    int h = lane >> 2;

    float4 q4 = ((const float4*)g_q)[(size_t)node * 32 + lane];
    int o  = g_off[node];
    int dg = g_deg[node];

    float4 acc = make_float4(0.f, 0.f, 0.f, 0.f);
    float sh = 0.f;

    for (int j = 0; j < dg; j++) {
        int src = g_csr_src[o + j];
        float bias = g_csr_bias[(size_t)(o + j) * HH + h];
        float4 k4 = ((const float4*)g_k)[(size_t)src * 32 + lane];
        float p = q4.x * k4.x + q4.y * k4.y + q4.z * k4.z + q4.w * k4.w;
        p += __shfl_xor_sync(0xffffffffu, p, 1);
        p += __shfl_xor_sync(0xffffffffu, p, 2);
        float ex = __expf(p * 0.25f + bias);
        sh += ex;
        float4 v4 = ((const float4*)g_v)[(size_t)src * 32 + lane];
        acc.x = fmaf(ex, v4.x, acc.x);
        acc.y = fmaf(ex, v4.y, acc.y);
        acc.z = fmaf(ex, v4.z, acc.z);
        acc.w = fmaf(ex, v4.w, acc.w);
    }

    float inv = 1.0f / fmaxf(sh, 1e-6f);
    acc.x *= inv; acc.y *= inv; acc.z *= inv; acc.w *= inv;
    ((float4*)g_agg)[(size_t)node * 32 + lane] = acc;
}

// ---------------- Wo GEMM + GroupNorm epilogue (fp32 SIMT) ---------
__global__ void out_gn_kernel(const float* __restrict__ Wo, const float* __restrict__ bo,
                              const float* __restrict__ gamma, const float* __restrict__ beta,
                              float* __restrict__ out) {
    __shared__ float xs[32 * 128];
    __shared__ float ws[64 * 128];

    const int row0 = blockIdx.x * 32;
    const int tid  = threadIdx.x;

    for (int i = tid; i < 32 * 32; i += 256) {
        int r  = i >> 5;
        int c4 = i & 31;
        float4 val = make_float4(0.f, 0.f, 0.f, 0.f);
        if (row0 + r < NN) val = ((const float4*)g_agg)[(size_t)(row0 + r) * 32 + c4];
        ((float4*)xs)[i] = val;
    }

    const int trow = tid >> 5;
    const int tcol = tid & 31;
    const int r = trow * 4;
    const int c = tcol * 4;

    float acc[4][4];
#pragma unroll
    for (int i = 0; i < 4; i++) {
#pragma unroll
        for (int j = 0; j < 4; j++) acc[i][j] = bo[c + j];
    }

#pragma unroll 1
    for (int kk = 0; kk < 128; kk += 64) {
        __syncthreads();
        for (int i = tid; i < 64 * 32; i += 256)
            ((float4*)ws)[i] = ((const float4*)Wo)[kk * 32 + i];
        __syncthreads();

#pragma unroll 8
        for (int k = 0; k < 64; k++) {
            float4 wv4 = ((float4*)ws)[k * 32 + tcol];
#pragma unroll
            for (int i = 0; i < 4; i++) {
                float a = xs[(r + i) * 128 + kk + k];
                acc[i][0] = fmaf(a, wv4.x, acc[i][0]);
                acc[i][1] = fmaf(a, wv4.y, acc[i][1]);
                acc[i][2] = fmaf(a, wv4.z, acc[i][2]);
                acc[i][3] = fmaf(a, wv4.w, acc[i][3]);
            }
        }
    }

    __syncthreads();
#pragma unroll
    for (int i = 0; i < 4; i++) {
#pragma unroll
        for (int j = 0; j < 4; j++) xs[(r + i) * 128 + c + j] = acc[i][j];
    }
    __syncthreads();

    int srow = tid >> 3;
    int grp  = tid & 7;
    float s = 0.f, s2 = 0.f;
#pragma unroll
    for (int j = 0; j < 16; j++) {
        float v = xs[srow * 128 + grp * 16 + j];
        s += v;
        s2 += v * v;
    }
    float mu  = s * (1.0f / 16.0f);
    float var = s2 * (1.0f / 16.0f) - mu * mu;
    float inv = rsqrtf(var + EPS_GN);

    if (row0 + srow < NN) {
        float* orow = out + (size_t)(row0 + srow) * 128;
#pragma unroll
        for (int j4 = 0; j4 < 4; j4++) {
            int ch0 = grp * 16 + j4 * 4;
            float4 g4 = ((const float4*)gamma)[ch0 >> 2];
            float4 b4 = ((const float4*)beta)[ch0 >> 2];
            float4 o;
            o.x = (xs[srow * 128 + ch0 + 0] - mu) * inv * g4.x + b4.x;
            o.y = (xs[srow * 128 + ch0 + 1] - mu) * inv * g4.y + b4.y;
            o.z = (xs[srow * 128 + ch0 + 2] - mu) * inv * g4.z + b4.z;
            o.w = (xs[srow * 128 + ch0 + 3] - mu) * inv * g4.w + b4.w;
            ((float4*)orow)[ch0 >> 2] = o;
        }
    }
}

// ---------------- launch ----------------
extern "C" void kernel_launch(void* const* d_in, const int* in_sizes, int n_in,
                              void* d_out, int out_size) {
    const float* x         = (const float*)d_in[0];
    const int*   ei        = (const int*)d_in[1];   // int32 (JAX downcasts int64 w/o x64 mode)
    const float* edge_attr = (const float*)d_in[2];
    const float* Wq        = (const float*)d_in[3];
    const float* bq        = (const float*)d_in[4];
    const float* Wk        = (const float*)d_in[5];
    const float* bk        = (const float*)d_in[6];
    const float* Wv        = (const float*)d_in[7];
    const float* bv        = (const float*)d_in[8];
    const float* We        = (const float*)d_in[9];
    const float* be        = (const float*)d_in[10];
    const float* Wo        = (const float*)d_in[11];
    const float* bo        = (const float*)d_in[12];
    const float* gamma     = (const float*)d_in[13];
    const float* beta      = (const float*)d_in[14];
    float* out = (float*)d_out;

    // CSR build
    zero_kernel<<<(NN + 255) / 256, 256>>>();
    hist_kernel<<<(EE + 255) / 256, 256>>>(ei);
    scan_kernel<<<1, 1024>>>();
    scatter_kernel<<<(EE + 255) / 256, 256>>>(ei, edge_attr, We, be);

    // projections
    qkv_tc_kernel<<<(NN + 127) / 128, 256>>>(x, Wq, bq, Wk, bk, Wv, bv);

    // fused attention gather (no atomics)
    gather_kernel<<<(NN + 7) / 8, 256>>>();

    // output projection + GroupNorm
    out_gn_kernel<<<(NN + 31) / 32, 256>>>(Wo, bo, gamma, beta, out);
}